// round 8
// baseline (speedup 1.0000x reference)
#include <cuda_runtime.h>
#define KNB 16
typedef unsigned u32;

__device__ __align__(256) float g_fA[20096 * 128];
__device__ __align__(256) float g_fB[20096 * 128];

__device__ __forceinline__ float sigf(float x) { return __fdividef(1.f, 1.f + __expf(-x)); }
__device__ __forceinline__ float thf(float x)  { return __fdividef(2.f, 1.f + __expf(-2.f * x)) - 1.f; }
__device__ __forceinline__ u32 tf32r(float f) {
    u32 r; asm("cvt.rna.tf32.f32 %0, %1;" : "=r"(r) : "f"(f)); return r;
}
__device__ __forceinline__ uint4 tf32x4(float4 v) {
    return make_uint4(tf32r(v.x), tf32r(v.y), tf32r(v.z), tf32r(v.w));
}
// D(16x8) += A(16x8,row) * B(8x8,col) ; tf32 inputs, fp32 accum
__device__ __forceinline__ void mma8(float* d, const u32* a, const u32* b) {
    asm volatile("mma.sync.aligned.m16n8k8.row.col.f32.tf32.tf32.f32 "
        "{%0,%1,%2,%3},{%4,%5,%6,%7},{%8,%9},{%0,%1,%2,%3};"
        : "+f"(d[0]), "+f"(d[1]), "+f"(d[2]), "+f"(d[3])
        : "r"(a[0]), "r"(a[1]), "r"(a[2]), "r"(a[3]), "r"(b[0]), "r"(b[1]));
}

__global__ void build_feat0(const float* __restrict__ p, float* __restrict__ f0, int nN) {
    int i = blockIdx.x * blockDim.x + threadIdx.x;
    if (i >= nN * 64) return;
    int node = i >> 6, k = i & 63;
    f0[i] = (k == 0) ? (16.0f / (float)nN) : p[node * 63 + (k - 1)];
}

// One GraphSAGE-LSTM layer on the tensor pipe via mma.sync tf32.
// CTA: 144 nodes (9 m-tiles), 384 threads (12 warps). Warp w: mg=w%3 owns
// m-tiles 3mg..3mg+2 (rows 48mg..48mg+47), ng=w/3 owns n-tiles 2ng,2ng+1 of
// each 64-gate chunk. Gates interleaved per unit: col 4u+{i,f,g,o}.
template <int DIN, int DOUT, bool RELU>
__global__ __launch_bounds__(384, 1)
void layer_mma(const float* __restrict__ fin, const int* __restrict__ nidx,
               const float* __restrict__ Wih, const float* __restrict__ Whh,
               const float* __restrict__ bih, const float* __restrict__ bhh,
               const float* __restrict__ Wself, const float* __restrict__ Wneigh,
               const float* __restrict__ bo, float* __restrict__ fout, int nN)
{
    constexpr int TM = 144, NT = 384, KK = 2 * DIN, D4 = DIN / 4, K4 = KK / 4;
    constexpr int SX = KK + 4;                 // float stride; SX%32==4 -> conflict-free frags
    constexpr int NCH = DIN / 16;              // 64-gate chunks per step
    constexpr int NPRE = (16 * KK + NT - 1) / NT;  // float4 per thread per W chunk

    extern __shared__ float sm[];
    float* Xs = sm;            // TM x SX : [x(DIN) | h(DIN) | pad]
    float* Ws = sm + TM * SX;  // 64 x SX : W chunk (tf32)
    __shared__ float BSI[512];
    __shared__ float BOs[128];

    const int tid = threadIdx.x, lane = tid & 31, w = tid >> 5;
    const int gq = lane >> 2, tq = lane & 3;
    const int mg = w % 3, ng = w / 3;
    const int MB = 48 * mg;
    const int node0 = blockIdx.x * TM;
    const float4* fin4 = (const float4*)fin;
    const float4* Wi4 = (const float4*)Wih;
    const float4* Wh4 = (const float4*)Whh;
    const float4* Wsf4 = (const float4*)Wself;
    const float4* Wng4 = (const float4*)Wneigh;

    // bias (interleaved: BSI[4u+q]), zero h, gather x(0)
    for (int e = tid; e < 4 * DIN; e += NT)
        BSI[e] = bih[(e & 3) * DIN + (e >> 2)] + bhh[(e & 3) * DIN + (e >> 2)];
    if (tid < DOUT) BOs[tid] = bo[tid];
    for (int e = tid; e < TM * D4; e += NT)
        ((uint4*)(Xs + (e / D4) * SX + DIN))[e % D4] = make_uint4(0, 0, 0, 0);
    for (int e = tid; e < TM * D4; e += NT) {
        int row = e / D4, k4 = e % D4;
        int nd = node0 + row; if (nd >= nN) nd = nN - 1;
        ((uint4*)(Xs + row * SX))[k4] = tf32x4(fin4[nidx[nd * KNB + 0] * D4 + k4]);
    }

    float c_loc[NCH][6], h_loc[NCH][6];
#pragma unroll 1
    for (int ci = 0; ci < NCH; ci++)
#pragma unroll
        for (int i = 0; i < 6; i++) c_loc[ci][i] = 0.f;

    // prefetch W chunk 0
    float4 pre[NPRE];
#pragma unroll
    for (int i = 0; i < NPRE; i++) {
        int idx = tid + i * NT;
        if (idx < 16 * KK) {
            int r = idx / K4, c4 = idx % K4;
            int wr = (r & 3) * DIN + (r >> 2);   // chunk 0
            pre[i] = (c4 < D4) ? Wi4[wr * D4 + c4] : Wh4[wr * D4 + c4 - D4];
        }
    }

    const float* pA0 = Xs + (MB + gq) * SX + tq;
    const float* pB0 = Ws + (16 * ng + gq) * SX + tq;

    for (int t = 0; t < KNB; t++) {
#pragma unroll 1
        for (int ci = 0; ci < NCH; ci++) {
            __syncthreads();   // Ws free / Xs writes visible
#pragma unroll
            for (int i = 0; i < NPRE; i++) {
                int idx = tid + i * NT;
                if (idx < 16 * KK)
                    ((uint4*)(Ws + (idx / K4) * SX))[idx % K4] = tf32x4(pre[i]);
            }
            __syncthreads();
            // prefetch next chunk (wraps to 0 for next step)
            int cn = (ci + 1 < NCH) ? ci + 1 : 0;
#pragma unroll
            for (int i = 0; i < NPRE; i++) {
                int idx = tid + i * NT;
                if (idx < 16 * KK) {
                    int r = idx / K4, c4 = idx % K4;
                    int wr = (r & 3) * DIN + cn * 16 + (r >> 2);
                    pre[i] = (c4 < D4) ? Wi4[wr * D4 + c4] : Wh4[wr * D4 + c4 - D4];
                }
            }
            // D init with bias
            float D[3][2][4];
#pragma unroll
            for (int nt = 0; nt < 2; nt++) {
                float b0 = BSI[ci * 64 + 16 * ng + 8 * nt + 2 * tq];
                float b1 = BSI[ci * 64 + 16 * ng + 8 * nt + 2 * tq + 1];
#pragma unroll
                for (int mi = 0; mi < 3; mi++) {
                    D[mi][nt][0] = b0; D[mi][nt][1] = b1;
                    D[mi][nt][2] = b0; D[mi][nt][3] = b1;
                }
            }
            // k loop
#pragma unroll 4
            for (int k0 = 0; k0 < KK; k0 += 8) {
                u32 a[3][4], b[2][2];
#pragma unroll
                for (int mi = 0; mi < 3; mi++) {
                    const float* pa = pA0 + 16 * mi * SX + k0;
                    a[mi][0] = __float_as_uint(pa[0]);
                    a[mi][1] = __float_as_uint(pa[8 * SX]);
                    a[mi][2] = __float_as_uint(pa[4]);
                    a[mi][3] = __float_as_uint(pa[8 * SX + 4]);
                }
#pragma unroll
                for (int nt = 0; nt < 2; nt++) {
                    const float* pb = pB0 + 8 * nt * SX + k0;
                    b[nt][0] = __float_as_uint(pb[0]);
                    b[nt][1] = __float_as_uint(pb[4]);
                }
#pragma unroll
                for (int mi = 0; mi < 3; mi++)
#pragma unroll
                    for (int nt = 0; nt < 2; nt++) mma8(D[mi][nt], a[mi], b[nt]);
            }
            // epilogue: reassemble gates via shfl, update c/h
#pragma unroll
            for (int mi = 0; mi < 3; mi++)
#pragma unroll
                for (int nt = 0; nt < 2; nt++) {
                    float d0 = D[mi][nt][0], d1 = D[mi][nt][1];
                    float d2 = D[mi][nt][2], d3 = D[mi][nt][3];
                    float x0 = __shfl_xor_sync(0xffffffffu, d0, 1);
                    float x1 = __shfl_xor_sync(0xffffffffu, d1, 1);
                    float x2 = __shfl_xor_sync(0xffffffffu, d2, 1);
                    float x3 = __shfl_xor_sync(0xffffffffu, d3, 1);
                    float gi, gf, gg, go;
                    if (!(tq & 1)) { gi = d0; gf = d1; gg = x0; go = x1; }  // row MB+16mi+gq
                    else           { gi = x2; gf = x3; gg = d2; go = d3; }  // row +8
                    float cc = sigf(gf) * c_loc[ci][mi * 2 + nt] + sigf(gi) * thf(gg);
                    c_loc[ci][mi * 2 + nt] = cc;
                    h_loc[ci][mi * 2 + nt] = __uint_as_float(tf32r(sigf(go) * thf(cc)));
                }
        }
        __syncthreads();  // all k-loop reads of h(t-1)/x(t) done
        // write back h(t)
#pragma unroll 1
        for (int ci = 0; ci < NCH; ci++)
#pragma unroll
            for (int mi = 0; mi < 3; mi++)
#pragma unroll
                for (int nt = 0; nt < 2; nt++) {
                    int row = MB + 16 * mi + gq + ((tq & 1) ? 8 : 0);
                    int u = ci * 16 + 4 * ng + 2 * nt + (tq >> 1);
                    Xs[row * SX + DIN + u] = h_loc[ci][mi * 2 + nt];
                }
        if (t + 1 < KNB) {  // gather x(t+1)
            for (int e = tid; e < TM * D4; e += NT) {
                int row = e / D4, k4 = e % D4;
                int nd = node0 + row; if (nd >= nN) nd = nN - 1;
                ((uint4*)(Xs + row * SX))[k4] = tf32x4(fin4[nidx[nd * KNB + t + 1] * D4 + k4]);
            }
        }
    }

    // ---- FC: out = [self_feat | h_final] @ [Wself|Wneigh]^T + b ----
    __syncthreads();
    for (int e = tid; e < TM * D4; e += NT) {
        int row = e / D4, k4 = e % D4;
        int nd = node0 + row; if (nd >= nN) nd = nN - 1;
        ((uint4*)(Xs + row * SX))[k4] = tf32x4(fin4[nd * D4 + k4]);
    }
    for (int ub = 0; ub < DOUT; ub += 64) {
        const int CR = (DOUT - ub < 64) ? (DOUT - ub) : 64;
        const int NTW = CR / 32;   // 2 (CR=64) or 1 (CR=32)
        __syncthreads();
        for (int e = tid; e < CR * K4; e += NT) {
            int r = e / K4, c4 = e % K4;
            int wr = ub + r;
            float4 v = (c4 < D4) ? Wsf4[wr * D4 + c4] : Wng4[wr * D4 + c4 - D4];
            ((uint4*)(Ws + r * SX))[c4] = tf32x4(v);
        }
        __syncthreads();
        float D[3][2][4];
        for (int nt = 0; nt < NTW; nt++) {
            int cb = 8 * (NTW * ng + nt);
            float b0 = BOs[ub + cb + 2 * tq], b1 = BOs[ub + cb + 2 * tq + 1];
#pragma unroll
            for (int mi = 0; mi < 3; mi++) {
                D[mi][nt][0] = b0; D[mi][nt][1] = b1;
                D[mi][nt][2] = b0; D[mi][nt][3] = b1;
            }
        }
#pragma unroll 4
        for (int k0 = 0; k0 < KK; k0 += 8) {
            u32 a[3][4], b[2][2];
#pragma unroll
            for (int mi = 0; mi < 3; mi++) {
                const float* pa = pA0 + 16 * mi * SX + k0;
                a[mi][0] = __float_as_uint(pa[0]);
                a[mi][1] = __float_as_uint(pa[8 * SX]);
                a[mi][2] = __float_as_uint(pa[4]);
                a[mi][3] = __float_as_uint(pa[8 * SX + 4]);
            }
            for (int nt = 0; nt < NTW; nt++) {
                const float* pb = Ws + (8 * (NTW * ng + nt) + gq) * SX + tq + k0;
                b[nt][0] = __float_as_uint(pb[0]);
                b[nt][1] = __float_as_uint(pb[4]);
            }
#pragma unroll
            for (int mi = 0; mi < 3; mi++)
                for (int nt = 0; nt < NTW; nt++) mma8(D[mi][nt], a[mi], b[nt]);
        }
#pragma unroll
        for (int mi = 0; mi < 3; mi++)
            for (int nt = 0; nt < NTW; nt++) {
                int col = ub + 8 * (NTW * ng + nt) + 2 * tq;
                int r0 = node0 + MB + 16 * mi + gq;
#pragma unroll
                for (int jj = 0; jj < 4; jj++) {
                    int nd = r0 + ((jj >> 1) ? 8 : 0);
                    if (nd < nN) {
                        float v = D[mi][nt][jj];
                        if (RELU) v = fmaxf(v, 0.f);
                        fout[nd * DOUT + col + (jj & 1)] = v;
                    }
                }
            }
    }
}

extern "C" void kernel_launch(void* const* d_in, const int* in_sizes, int n_in,
                              void* d_out, int out_size) {
    const float* p  = (const float*)d_in[0];
    const int* nidx = (const int*)d_in[1];
    int nN = in_sizes[1] / KNB;

    float *fA, *fB;
    cudaGetSymbolAddress((void**)&fA, g_fA);
    cudaGetSymbolAddress((void**)&fB, g_fB);

    int smA = (144 + 64) * (2 * 64 + 4) * 4;    // DIN=64  -> 109,824
    int smB = (144 + 64) * (2 * 128 + 4) * 4;   // DIN=128 -> 216,320
    cudaFuncSetAttribute(layer_mma<64, 128, true>,  cudaFuncAttributeMaxDynamicSharedMemorySize, smA);
    cudaFuncSetAttribute(layer_mma<128, 128, true>, cudaFuncAttributeMaxDynamicSharedMemorySize, smB);
    cudaFuncSetAttribute(layer_mma<128, 32, false>, cudaFuncAttributeMaxDynamicSharedMemorySize, smB);

    build_feat0<<<(nN * 64 + 255) / 256, 256>>>(p, fA, nN);

    int grid = (nN + 143) / 144;
    layer_mma<64, 128, true><<<grid, 384, smA>>>(
        fA, nidx, (const float*)d_in[2], (const float*)d_in[3], (const float*)d_in[4],
        (const float*)d_in[5], (const float*)d_in[6], (const float*)d_in[7],
        (const float*)d_in[8], fB, nN);
    layer_mma<128, 128, true><<<grid, 384, smB>>>(
        fB, nidx, (const float*)d_in[9], (const float*)d_in[10], (const float*)d_in[11],
        (const float*)d_in[12], (const float*)d_in[13], (const float*)d_in[14],
        (const float*)d_in[15], fA, nN);
    layer_mma<128, 32, false><<<grid, 384, smB>>>(
        fA, nidx, (const float*)d_in[16], (const float*)d_in[17], (const float*)d_in[18],
        (const float*)d_in[19], (const float*)d_in[20], (const float*)d_in[21],
        (const float*)d_in[22], (float*)d_out, nN);
}

// round 9
// speedup vs baseline: 1.2707x; 1.2707x over previous
#include <cuda_runtime.h>
#define KNB 16
typedef unsigned u32;

__device__ __align__(256) float g_fA[20096 * 128];
__device__ __align__(256) float g_fB[20096 * 128];
__device__ __align__(256) float g_gX[20096 * 640];

__device__ __forceinline__ float sigf(float x) { return __fdividef(1.f, 1.f + __expf(-x)); }
__device__ __forceinline__ float thf(float x)  { return __fdividef(2.f, 1.f + __expf(-2.f * x)) - 1.f; }
__device__ __forceinline__ u32 tf32r(float f) {
    u32 r; asm("cvt.rna.tf32.f32 %0, %1;" : "=r"(r) : "f"(f)); return r;
}
__device__ __forceinline__ uint4 tf32x4(float4 v) {
    return make_uint4(tf32r(v.x), tf32r(v.y), tf32r(v.z), tf32r(v.w));
}
__device__ __forceinline__ void mma8(float* d, const u32* a, const u32* b) {
    asm volatile("mma.sync.aligned.m16n8k8.row.col.f32.tf32.tf32.f32 "
        "{%0,%1,%2,%3},{%4,%5,%6,%7},{%8,%9},{%0,%1,%2,%3};"
        : "+f"(d[0]), "+f"(d[1]), "+f"(d[2]), "+f"(d[3])
        : "r"(a[0]), "r"(a[1]), "r"(a[2]), "r"(a[3]), "r"(b[0]), "r"(b[1]));
}

__global__ void build_feat0(const float* __restrict__ p, float* __restrict__ f0, int nN) {
    int i = blockIdx.x * blockDim.x + threadIdx.x;
    if (i >= nN * 64) return;
    int node = i >> 6, k = i & 63;
    f0[i] = (k == 0) ? (16.0f / (float)nN) : p[node * 63 + (k - 1)];
}

// ---------------- precompute: gX[n] = feat[n] @ [Wih(interleaved) | Wself]^T + bias ----------------
// gate cols: 4u+q (q = i,f,g,o); self cols appended at 4*DIN.
template <int DIN, int DOUT>
__global__ __launch_bounds__(384, 1)
void pre_k(const float* __restrict__ feat,
           const float* __restrict__ Wih, const float* __restrict__ bih,
           const float* __restrict__ bhh, const float* __restrict__ Wself,
           const float* __restrict__ bo, float* __restrict__ gX, int nN)
{
    constexpr int TM = 144, NT = 384, K4 = DIN / 4, SXA = DIN + 4, W = 4 * DIN + DOUT;
    extern __shared__ float sm[];
    float* Xs = sm;                 // TM x SXA (tf32 feat)
    float* Ws = sm + TM * SXA;      // 128 x SXA
    float* CB = Ws + 128 * SXA;     // W combined bias

    const int tid = threadIdx.x, lane = tid & 31, w = tid >> 5;
    const int gq = lane >> 2, tq = lane & 3, mg = w % 3, ng = w / 3, MB = 48 * mg;
    const int node0 = blockIdx.x * TM;
    const float4* fin4 = (const float4*)feat;
    const float4* Wi4 = (const float4*)Wih;
    const float4* Wsf4 = (const float4*)Wself;

    for (int e = tid; e < 4 * DIN; e += NT)
        CB[e] = bih[(e & 3) * DIN + (e >> 2)] + bhh[(e & 3) * DIN + (e >> 2)];
    for (int e = tid; e < DOUT; e += NT) CB[4 * DIN + e] = bo[e];
    for (int e = tid; e < TM * K4; e += NT) {
        int row = e / K4, c4 = e % K4;
        int nd = node0 + row; if (nd >= nN) nd = nN - 1;
        ((uint4*)(Xs + row * SXA))[c4] = tf32x4(fin4[nd * K4 + c4]);
    }
    const float* pA0 = Xs + (MB + gq) * SXA + tq;

    for (int c0 = 0; c0 < W; c0 += 128) {
        const int CR = (W - c0 < 128) ? (W - c0) : 128;
        const int NTW = CR / 32, CG = CR / 4;
        __syncthreads();
        for (int e = tid; e < CR * K4; e += NT) {
            int r = e / K4, c4 = e % K4;
            int gc = c0 + r;
            float4 v = (gc < 4 * DIN) ? Wi4[((gc & 3) * DIN + (gc >> 2)) * K4 + c4]
                                      : Wsf4[(gc - 4 * DIN) * K4 + c4];
            ((uint4*)(Ws + r * SXA))[c4] = tf32x4(v);
        }
        __syncthreads();
        float D[3][4][4];
        for (int nt = 0; nt < NTW; nt++) {
            float b0 = CB[c0 + CG * ng + 8 * nt + 2 * tq];
            float b1 = CB[c0 + CG * ng + 8 * nt + 2 * tq + 1];
#pragma unroll
            for (int mi = 0; mi < 3; mi++) {
                D[mi][nt][0] = b0; D[mi][nt][1] = b1;
                D[mi][nt][2] = b0; D[mi][nt][3] = b1;
            }
        }
#pragma unroll 4
        for (int k0 = 0; k0 < DIN; k0 += 8) {
            u32 a[3][4], b[4][2];
#pragma unroll
            for (int mi = 0; mi < 3; mi++) {
                const float* pa = pA0 + 16 * mi * SXA + k0;
                a[mi][0] = __float_as_uint(pa[0]);
                a[mi][1] = __float_as_uint(pa[8 * SXA]);
                a[mi][2] = __float_as_uint(pa[4]);
                a[mi][3] = __float_as_uint(pa[8 * SXA + 4]);
            }
            for (int nt = 0; nt < NTW; nt++) {
                const float* pb = Ws + (CG * ng + 8 * nt + gq) * SXA + tq + k0;
                b[nt][0] = __float_as_uint(pb[0]);
                b[nt][1] = __float_as_uint(pb[4]);
#pragma unroll
                for (int mi = 0; mi < 3; mi++) mma8(D[mi][nt], a[mi], b[nt]);
            }
        }
        for (int nt = 0; nt < NTW; nt++) {
            int col = c0 + CG * ng + 8 * nt + 2 * tq;
#pragma unroll
            for (int mi = 0; mi < 3; mi++) {
                int r0 = node0 + MB + 16 * mi + gq;
                if (r0 < nN) {
                    gX[r0 * W + col] = D[mi][nt][0];
                    gX[r0 * W + col + 1] = D[mi][nt][1];
                }
                if (r0 + 8 < nN) {
                    gX[(r0 + 8) * W + col] = D[mi][nt][2];
                    gX[(r0 + 8) * W + col + 1] = D[mi][nt][3];
                }
            }
        }
    }
}

// ---------------- recurrent: h(t) from h(t-1) @ Whh^T + gathered precomputed x-gates ----------------
template <int DIN, int DOUT, bool RELU>
__global__ __launch_bounds__(384, 1)
void rec_k(const float* __restrict__ gX, const int* __restrict__ nidx,
           const float* __restrict__ Whh, const float* __restrict__ Wneigh,
           float* __restrict__ fout, int nN)
{
    constexpr int TM = 144, NT = 384, K4 = DIN / 4, SXA = DIN + 4, SXG = 136;
    constexpr int W = 4 * DIN + DOUT, NCHG = (4 * DIN) / 128;
    extern __shared__ float sm[];
    float* Xs = sm;                    // TM x SXA : h (tf32)
    float* Ws = sm + TM * SXA;         // 128 x SXA : Whh chunk / Wneigh
    float* Gs = Ws + 128 * SXA;        // TM x SXG : gathered x-gates / selfX

    const int tid = threadIdx.x, lane = tid & 31, w = tid >> 5;
    const int gq = lane >> 2, tq = lane & 3, mg = w % 3, ng = w / 3, MB = 48 * mg;
    const int node0 = blockIdx.x * TM;
    const float4* Wh4 = (const float4*)Whh;
    const float4* Wn4 = (const float4*)Wneigh;

    for (int e = tid; e < TM * K4; e += NT)
        ((uint4*)(Xs + (e / K4) * SXA))[e % K4] = make_uint4(0, 0, 0, 0);

    float c_loc[NCHG][12], h_loc[NCHG][12];
#pragma unroll 1
    for (int ci = 0; ci < NCHG; ci++)
#pragma unroll
        for (int i = 0; i < 12; i++) c_loc[ci][i] = 0.f;

    const float* pA0 = Xs + (MB + gq) * SXA + tq;

    for (int t = 0; t < KNB; t++) {
#pragma unroll 1
        for (int ci = 0; ci < NCHG; ci++) {
            __syncthreads();
            // stage Whh chunk: 128 gate rows (interleaved 4u+q) x DIN
            for (int e = tid; e < 128 * K4; e += NT) {
                int r = e / K4, c4 = e % K4;
                int gc = ci * 128 + r;
                ((uint4*)(Ws + r * SXA))[c4] = tf32x4(Wh4[((gc & 3) * DIN + (gc >> 2)) * K4 + c4]);
            }
            // stage gathered x-gates for this chunk
            for (int e = tid; e < TM * 32; e += NT) {
                int row = e >> 5, c4 = e & 31;
                int nd = node0 + row; if (nd >= nN) nd = nN - 1;
                int src = nidx[nd * KNB + t];
                ((float4*)(Gs + row * SXG))[c4] =
                    ((const float4*)(gX + src * W + ci * 128))[c4];
            }
            __syncthreads();
            float D[3][4][4];
#pragma unroll
            for (int mi = 0; mi < 3; mi++)
#pragma unroll
                for (int nt = 0; nt < 4; nt++) {
                    const float* pg = Gs + (MB + 16 * mi + gq) * SXG + 32 * ng + 8 * nt + 2 * tq;
                    D[mi][nt][0] = pg[0]; D[mi][nt][1] = pg[1];
                    D[mi][nt][2] = pg[8 * SXG]; D[mi][nt][3] = pg[8 * SXG + 1];
                }
#pragma unroll 4
            for (int k0 = 0; k0 < DIN; k0 += 8) {
                u32 a[3][4], b[4][2];
#pragma unroll
                for (int mi = 0; mi < 3; mi++) {
                    const float* pa = pA0 + 16 * mi * SXA + k0;
                    a[mi][0] = __float_as_uint(pa[0]);
                    a[mi][1] = __float_as_uint(pa[8 * SXA]);
                    a[mi][2] = __float_as_uint(pa[4]);
                    a[mi][3] = __float_as_uint(pa[8 * SXA + 4]);
                }
#pragma unroll
                for (int nt = 0; nt < 4; nt++) {
                    const float* pb = Ws + (32 * ng + 8 * nt + gq) * SXA + tq + k0;
                    b[nt][0] = __float_as_uint(pb[0]);
                    b[nt][1] = __float_as_uint(pb[4]);
#pragma unroll
                    for (int mi = 0; mi < 3; mi++) mma8(D[mi][nt], a[mi], b[nt]);
                }
            }
            // epilogue: reassemble gates via shfl, update c, stash h
#pragma unroll
            for (int mi = 0; mi < 3; mi++)
#pragma unroll
                for (int nt = 0; nt < 4; nt++) {
                    float d0 = D[mi][nt][0], d1 = D[mi][nt][1];
                    float d2 = D[mi][nt][2], d3 = D[mi][nt][3];
                    float x0 = __shfl_xor_sync(0xffffffffu, d0, 1);
                    float x1 = __shfl_xor_sync(0xffffffffu, d1, 1);
                    float x2 = __shfl_xor_sync(0xffffffffu, d2, 1);
                    float x3 = __shfl_xor_sync(0xffffffffu, d3, 1);
                    float gi, gf, gg, go;
                    if (!(tq & 1)) { gi = d0; gf = d1; gg = x0; go = x1; }
                    else           { gi = x2; gf = x3; gg = d2; go = d3; }
                    int s = mi * 4 + nt;
                    float cc = sigf(gf) * c_loc[ci][s] + sigf(gi) * thf(gg);
                    c_loc[ci][s] = cc;
                    h_loc[ci][s] = __uint_as_float(tf32r(sigf(go) * thf(cc)));
                }
        }
        __syncthreads();
        // write h(t)
#pragma unroll 1
        for (int ci = 0; ci < NCHG; ci++)
#pragma unroll
            for (int mi = 0; mi < 3; mi++)
#pragma unroll
                for (int nt = 0; nt < 4; nt++) {
                    int row = MB + 16 * mi + gq + ((tq & 1) ? 8 : 0);
                    int u = ci * 32 + 8 * ng + 2 * nt + (tq >> 1);
                    Xs[row * SXA + u] = h_loc[ci][mi * 4 + nt];
                }
    }

    // ---- FC: out = selfX (precomputed) + h_final @ Wneigh^T ----
    constexpr int CR = DOUT, NTW = CR / 32 ? CR / 32 : 1, CG = CR / 4;
    __syncthreads();
    for (int e = tid; e < CR * K4; e += NT) {
        int r = e / K4, c4 = e % K4;
        ((uint4*)(Ws + r * SXA))[c4] = tf32x4(Wn4[r * K4 + c4]);
    }
    for (int e = tid; e < TM * (CR / 4); e += NT) {
        int row = e / (CR / 4), c4 = e % (CR / 4);
        int nd = node0 + row; if (nd >= nN) nd = nN - 1;
        ((float4*)(Gs + row * SXG))[c4] =
            ((const float4*)(gX + nd * W + 4 * DIN))[c4];
    }
    __syncthreads();
    float D[3][4][4];
#pragma unroll
    for (int mi = 0; mi < 3; mi++)
        for (int nt = 0; nt < NTW; nt++) {
            const float* pg = Gs + (MB + 16 * mi + gq) * SXG + CG * ng + 8 * nt + 2 * tq;
            D[mi][nt][0] = pg[0]; D[mi][nt][1] = pg[1];
            D[mi][nt][2] = pg[8 * SXG]; D[mi][nt][3] = pg[8 * SXG + 1];
        }
#pragma unroll 4
    for (int k0 = 0; k0 < DIN; k0 += 8) {
        u32 a[3][4], b[4][2];
#pragma unroll
        for (int mi = 0; mi < 3; mi++) {
            const float* pa = pA0 + 16 * mi * SXA + k0;
            a[mi][0] = __float_as_uint(pa[0]);
            a[mi][1] = __float_as_uint(pa[8 * SXA]);
            a[mi][2] = __float_as_uint(pa[4]);
            a[mi][3] = __float_as_uint(pa[8 * SXA + 4]);
        }
        for (int nt = 0; nt < NTW; nt++) {
            const float* pb = Ws + (CG * ng + 8 * nt + gq) * SXA + tq + k0;
            b[nt][0] = __float_as_uint(pb[0]);
            b[nt][1] = __float_as_uint(pb[4]);
#pragma unroll
            for (int mi = 0; mi < 3; mi++) mma8(D[mi][nt], a[mi], b[nt]);
        }
    }
    for (int nt = 0; nt < NTW; nt++) {
        int col = CG * ng + 8 * nt + 2 * tq;
#pragma unroll
        for (int mi = 0; mi < 3; mi++) {
            int r0 = node0 + MB + 16 * mi + gq;
            if (r0 < nN) {
                float v0 = D[mi][nt][0], v1 = D[mi][nt][1];
                if (RELU) { v0 = fmaxf(v0, 0.f); v1 = fmaxf(v1, 0.f); }
                fout[r0 * DOUT + col] = v0; fout[r0 * DOUT + col + 1] = v1;
            }
            if (r0 + 8 < nN) {
                float v2 = D[mi][nt][2], v3 = D[mi][nt][3];
                if (RELU) { v2 = fmaxf(v2, 0.f); v3 = fmaxf(v3, 0.f); }
                fout[(r0 + 8) * DOUT + col] = v2; fout[(r0 + 8) * DOUT + col + 1] = v3;
            }
        }
    }
}

extern "C" void kernel_launch(void* const* d_in, const int* in_sizes, int n_in,
                              void* d_out, int out_size) {
    const float* p  = (const float*)d_in[0];
    const int* nidx = (const int*)d_in[1];
    int nN = in_sizes[1] / KNB;

    float *fA, *fB, *gX;
    cudaGetSymbolAddress((void**)&fA, g_fA);
    cudaGetSymbolAddress((void**)&fB, g_fB);
    cudaGetSymbolAddress((void**)&gX, g_gX);

    auto smPre = [](int DIN, int DOUT) {
        return (144 * (DIN + 4) + 128 * (DIN + 4) + 4 * DIN + DOUT) * 4;
    };
    auto smRec = [](int DIN) {
        return (144 * (DIN + 4) + 128 * (DIN + 4) + 144 * 136) * 4;
    };
    cudaFuncSetAttribute(pre_k<64, 128>,  cudaFuncAttributeMaxDynamicSharedMemorySize, smPre(64, 128));
    cudaFuncSetAttribute(pre_k<128, 128>, cudaFuncAttributeMaxDynamicSharedMemorySize, smPre(128, 128));
    cudaFuncSetAttribute(pre_k<128, 32>,  cudaFuncAttributeMaxDynamicSharedMemorySize, smPre(128, 32));
    cudaFuncSetAttribute(rec_k<64, 128, true>,  cudaFuncAttributeMaxDynamicSharedMemorySize, smRec(64));
    cudaFuncSetAttribute(rec_k<128, 128, true>, cudaFuncAttributeMaxDynamicSharedMemorySize, smRec(128));
    cudaFuncSetAttribute(rec_k<128, 32, false>, cudaFuncAttributeMaxDynamicSharedMemorySize, smRec(128));

    build_feat0<<<(nN * 64 + 255) / 256, 256>>>(p, fA, nN);

    int grid = (nN + 143) / 144;
    // layer 0
    pre_k<64, 128><<<grid, 384, smPre(64, 128)>>>(
        fA, (const float*)d_in[2], (const float*)d_in[4], (const float*)d_in[5],
        (const float*)d_in[6], (const float*)d_in[8], gX, nN);
    rec_k<64, 128, true><<<grid, 384, smRec(64)>>>(
        gX, nidx, (const float*)d_in[3], (const float*)d_in[7], fB, nN);
    // layer 1
    pre_k<128, 128><<<grid, 384, smPre(128, 128)>>>(
        fB, (const float*)d_in[9], (const float*)d_in[11], (const float*)d_in[12],
        (const float*)d_in[13], (const float*)d_in[15], gX, nN);
    rec_k<128, 128, true><<<grid, 384, smRec(128)>>>(
        gX, nidx, (const float*)d_in[10], (const float*)d_in[14], fA, nN);
    // layer 2
    pre_k<128, 32><<<grid, 384, smPre(128, 32)>>>(
        fA, (const float*)d_in[16], (const float*)d_in[18], (const float*)d_in[19],
        (const float*)d_in[20], (const float*)d_in[22], gX, nN);
    rec_k<128, 32, false><<<grid, 384, smRec(128)>>>(
        gX, nidx, (const float*)d_in[17], (const float*)d_in[21], (float*)d_out, nN);
}

// round 10
// speedup vs baseline: 1.4540x; 1.1443x over previous
#include <cuda_runtime.h>
#define KNB 16
typedef unsigned u32;

__device__ __align__(256) float g_fA[20096 * 128];
__device__ __align__(256) float g_fB[20096 * 128];
__device__ __align__(256) float g_gX[20096 * 640];

__device__ __forceinline__ float tanha(float x) {
    float r; asm("tanh.approx.f32 %0, %1;" : "=f"(r) : "f"(x)); return r;
}
__device__ __forceinline__ float siga(float x) {
    return fmaf(tanha(0.5f * x), 0.5f, 0.5f);
}
__device__ __forceinline__ u32 tf32r(float f) {
    u32 r; asm("cvt.rna.tf32.f32 %0, %1;" : "=r"(r) : "f"(f)); return r;
}
__device__ __forceinline__ uint4 tf32x4(float4 v) {
    return make_uint4(tf32r(v.x), tf32r(v.y), tf32r(v.z), tf32r(v.w));
}
__device__ __forceinline__ void mma8(float* d, const u32* a, const u32* b) {
    asm volatile("mma.sync.aligned.m16n8k8.row.col.f32.tf32.tf32.f32 "
        "{%0,%1,%2,%3},{%4,%5,%6,%7},{%8,%9},{%0,%1,%2,%3};"
        : "+f"(d[0]), "+f"(d[1]), "+f"(d[2]), "+f"(d[3])
        : "r"(a[0]), "r"(a[1]), "r"(a[2]), "r"(a[3]), "r"(b[0]), "r"(b[1]));
}
// Gate-column permutation: output col c (< 4*DIN) holds source gate row gmap(c).
// Decode: block=c>>5 (8 units per 32-col block), w5=c&31, nt=w5>>3, tq=(w5>>1)&3,
// e=w5&1 -> gate q=2*(nt&1)+e, unit=block*8+(nt>>1)*4+tq. Thread (gq,tq) of warp ng
// then owns all 4 gates of its units directly in its MMA output regs (no shfl).
__device__ __forceinline__ int gmap(int c, int DIN) {
    int blk = c >> 5, w5 = c & 31;
    int nt = w5 >> 3, tq = (w5 >> 1) & 3, e = w5 & 1;
    return (2 * (nt & 1) + e) * DIN + blk * 8 + (nt >> 1) * 4 + tq;
}

__global__ void build_feat0(const float* __restrict__ p, float* __restrict__ f0, int nN) {
    int i = blockIdx.x * blockDim.x + threadIdx.x;
    if (i >= nN * 64) return;
    int node = i >> 6, k = i & 63;
    f0[i] = (k == 0) ? (16.0f / (float)nN) : p[node * 63 + (k - 1)];
}

// ---------------- precompute: gX[n] = feat[n] @ [Wih(permuted) | Wself]^T + bias ----------------
template <int DIN, int DOUT>
__global__ __launch_bounds__(384, 1)
void pre_k(const float* __restrict__ feat,
           const float* __restrict__ Wih, const float* __restrict__ bih,
           const float* __restrict__ bhh, const float* __restrict__ Wself,
           const float* __restrict__ bo, float* __restrict__ gX, int nN)
{
    constexpr int TM = 144, NT = 384, K4 = DIN / 4, SXA = DIN + 4, W = 4 * DIN + DOUT;
    extern __shared__ float sm[];
    float* Xs = sm;
    float* Ws = sm + TM * SXA;
    float* CB = Ws + 128 * SXA;

    const int tid = threadIdx.x, lane = tid & 31, w = tid >> 5;
    const int gq = lane >> 2, tq = lane & 3, mg = w % 3, ng = w / 3, MB = 48 * mg;
    const int node0 = blockIdx.x * TM;
    const float4* fin4 = (const float4*)feat;
    const float4* Wi4 = (const float4*)Wih;
    const float4* Wsf4 = (const float4*)Wself;

    for (int e = tid; e < 4 * DIN; e += NT) {
        int sr = gmap(e, DIN);
        CB[e] = bih[sr] + bhh[sr];
    }
    for (int e = tid; e < DOUT; e += NT) CB[4 * DIN + e] = bo[e];
    for (int e = tid; e < TM * K4; e += NT) {
        int row = e / K4, c4 = e % K4;
        int nd = node0 + row; if (nd >= nN) nd = nN - 1;
        ((uint4*)(Xs + row * SXA))[c4] = tf32x4(fin4[nd * K4 + c4]);
    }
    const float* pA0 = Xs + (MB + gq) * SXA + tq;

    for (int c0 = 0; c0 < W; c0 += 128) {
        const int CR = (W - c0 < 128) ? (W - c0) : 128;
        const int NTW = CR / 32, CG = CR / 4;
        __syncthreads();
        for (int e = tid; e < CR * K4; e += NT) {
            int r = e / K4, c4 = e % K4;
            int gc = c0 + r;
            float4 v = (gc < 4 * DIN) ? Wi4[gmap(gc, DIN) * K4 + c4]
                                      : Wsf4[(gc - 4 * DIN) * K4 + c4];
            ((uint4*)(Ws + r * SXA))[c4] = tf32x4(v);
        }
        __syncthreads();
        float D[3][4][4];
        for (int nt = 0; nt < NTW; nt++) {
            float b0 = CB[c0 + CG * ng + 8 * nt + 2 * tq];
            float b1 = CB[c0 + CG * ng + 8 * nt + 2 * tq + 1];
#pragma unroll
            for (int mi = 0; mi < 3; mi++) {
                D[mi][nt][0] = b0; D[mi][nt][1] = b1;
                D[mi][nt][2] = b0; D[mi][nt][3] = b1;
            }
        }
#pragma unroll 4
        for (int k0 = 0; k0 < DIN; k0 += 8) {
            u32 a[3][4], b[4][2];
#pragma unroll
            for (int mi = 0; mi < 3; mi++) {
                const float* pa = pA0 + 16 * mi * SXA + k0;
                a[mi][0] = __float_as_uint(pa[0]);
                a[mi][1] = __float_as_uint(pa[8 * SXA]);
                a[mi][2] = __float_as_uint(pa[4]);
                a[mi][3] = __float_as_uint(pa[8 * SXA + 4]);
            }
            for (int nt = 0; nt < NTW; nt++) {
                const float* pb = Ws + (CG * ng + 8 * nt + gq) * SXA + tq + k0;
                b[nt][0] = __float_as_uint(pb[0]);
                b[nt][1] = __float_as_uint(pb[4]);
#pragma unroll
                for (int mi = 0; mi < 3; mi++) mma8(D[mi][nt], a[mi], b[nt]);
            }
        }
        for (int nt = 0; nt < NTW; nt++) {
            int col = c0 + CG * ng + 8 * nt + 2 * tq;
#pragma unroll
            for (int mi = 0; mi < 3; mi++) {
                int r0 = node0 + MB + 16 * mi + gq;
                if (r0 < nN) {
                    gX[r0 * W + col] = D[mi][nt][0];
                    gX[r0 * W + col + 1] = D[mi][nt][1];
                }
                if (r0 + 8 < nN) {
                    gX[(r0 + 8) * W + col] = D[mi][nt][2];
                    gX[(r0 + 8) * W + col + 1] = D[mi][nt][3];
                }
            }
        }
    }
}

// ---------------- recurrent: h(t) = LSTM(h(t-1) @ Whh^T + gathered x-gates) ----------------
template <int DIN, int DOUT, bool RELU>
__global__ __launch_bounds__(384, 1)
void rec_k(const float* __restrict__ gX, const int* __restrict__ nidx,
           const float* __restrict__ Whh, const float* __restrict__ Wneigh,
           float* __restrict__ fout, int nN)
{
    constexpr int TM = 144, NT = 384, K4 = DIN / 4, SXA = DIN + 4, SXG = 132;
    constexpr int W = 4 * DIN + DOUT, W4 = W / 4, NCHG = (4 * DIN) / 128;
    constexpr int NPRE = (128 * K4 + NT - 1) / NT;
    extern __shared__ float sm[];
    float* Xs = sm;                    // TM x SXA : h (tf32)
    float* Ws = sm + TM * SXA;         // 128 x SXA : Whh chunk / Wneigh
    float* Gs = Ws + 128 * SXA;        // TM x SXG : gathered x-gates / selfX

    const int tid = threadIdx.x, lane = tid & 31, w = tid >> 5;
    const int gq = lane >> 2, tq = lane & 3, mg = w % 3, ng = w / 3, MB = 48 * mg;
    const int node0 = blockIdx.x * TM;
    const float4* Wh4 = (const float4*)Whh;
    const float4* Wn4 = (const float4*)Wneigh;
    const float4* gX4 = (const float4*)gX;

    for (int e = tid; e < TM * K4; e += NT)
        ((uint4*)(Xs + (e / K4) * SXA))[e % K4] = make_uint4(0, 0, 0, 0);

    float c_loc[NCHG][12], h_loc[NCHG][12];
#pragma unroll 1
    for (int ci = 0; ci < NCHG; ci++)
#pragma unroll
        for (int i = 0; i < 12; i++) c_loc[ci][i] = 0.f;

    // prefetch Whh chunk 0 into registers
    float4 pre[NPRE];
#pragma unroll
    for (int i = 0; i < NPRE; i++) {
        int idx = tid + i * NT;
        if (idx < 128 * K4)
            pre[i] = Wh4[gmap(idx / K4, DIN) * K4 + idx % K4];
    }

    const float* pA0 = Xs + (MB + gq) * SXA + tq;

    for (int t = 0; t < KNB; t++) {
#pragma unroll 1
        for (int ci = 0; ci < NCHG; ci++) {
            __syncthreads();   // Ws/Gs free; h(t-1) visible
            // commit prefetched Whh chunk
#pragma unroll
            for (int i = 0; i < NPRE; i++) {
                int idx = tid + i * NT;
                if (idx < 128 * K4)
                    ((uint4*)(Ws + (idx / K4) * SXA))[idx % K4] = tf32x4(pre[i]);
            }
            // stage gathered x-gates for this chunk
            for (int e = tid; e < TM * 32; e += NT) {
                int row = e >> 5, c4 = e & 31;
                int nd = node0 + row; if (nd >= nN) nd = nN - 1;
                int src = nidx[nd * KNB + t];
                ((float4*)(Gs + row * SXG))[c4] = gX4[src * W4 + ci * 32 + c4];
            }
            __syncthreads();
            // prefetch next chunk (wraps; Whh identical across t)
            int cn = (ci + 1 < NCHG) ? ci + 1 : 0;
#pragma unroll
            for (int i = 0; i < NPRE; i++) {
                int idx = tid + i * NT;
                if (idx < 128 * K4)
                    pre[i] = Wh4[gmap(cn * 128 + idx / K4, DIN) * K4 + idx % K4];
            }
            // D init from gathered gates
            float D[3][4][4];
#pragma unroll
            for (int mi = 0; mi < 3; mi++)
#pragma unroll
                for (int nt = 0; nt < 4; nt++) {
                    const float* pg = Gs + (MB + 16 * mi + gq) * SXG + 32 * ng + 8 * nt + 2 * tq;
                    D[mi][nt][0] = pg[0]; D[mi][nt][1] = pg[1];
                    D[mi][nt][2] = pg[8 * SXG]; D[mi][nt][3] = pg[8 * SXG + 1];
                }
#pragma unroll 4
            for (int k0 = 0; k0 < DIN; k0 += 8) {
                u32 a[3][4], b[4][2];
#pragma unroll
                for (int mi = 0; mi < 3; mi++) {
                    const float* pa = pA0 + 16 * mi * SXA + k0;
                    a[mi][0] = __float_as_uint(pa[0]);
                    a[mi][1] = __float_as_uint(pa[8 * SXA]);
                    a[mi][2] = __float_as_uint(pa[4]);
                    a[mi][3] = __float_as_uint(pa[8 * SXA + 4]);
                }
#pragma unroll
                for (int nt = 0; nt < 4; nt++) {
                    const float* pb = Ws + (32 * ng + 8 * nt + gq) * SXA + tq + k0;
                    b[nt][0] = __float_as_uint(pb[0]);
                    b[nt][1] = __float_as_uint(pb[4]);
#pragma unroll
                    for (int mi = 0; mi < 3; mi++) mma8(D[mi][nt], a[mi], b[nt]);
                }
            }
            // epilogue: each thread owns all 4 gates of its cells (no shfl)
#pragma unroll
            for (int mi = 0; mi < 3; mi++)
#pragma unroll
                for (int up = 0; up < 2; up++)
#pragma unroll
                    for (int r2 = 0; r2 < 2; r2++) {
                        float gi = D[mi][2 * up][2 * r2];
                        float gf = D[mi][2 * up][2 * r2 + 1];
                        float gg = D[mi][2 * up + 1][2 * r2];
                        float go = D[mi][2 * up + 1][2 * r2 + 1];
                        int s = (mi * 2 + up) * 2 + r2;
                        float cc = siga(gf) * c_loc[ci][s] + siga(gi) * tanha(gg);
                        c_loc[ci][s] = cc;
                        h_loc[ci][s] = __uint_as_float(tf32r(siga(go) * tanha(cc)));
                    }
        }
        __syncthreads();  // all Xs reads done
        // write h(t): unit u = ci*32 + 8*ng + 4*up + tq
#pragma unroll 1
        for (int ci = 0; ci < NCHG; ci++)
#pragma unroll
            for (int mi = 0; mi < 3; mi++)
#pragma unroll
                for (int up = 0; up < 2; up++)
#pragma unroll
                    for (int r2 = 0; r2 < 2; r2++) {
                        int row = MB + 16 * mi + gq + 8 * r2;
                        int u = ci * 32 + 8 * ng + 4 * up + tq;
                        Xs[row * SXA + u] = h_loc[ci][(mi * 2 + up) * 2 + r2];
                    }
    }

    // ---- FC: out = selfX (precomputed, bias folded) + h_final @ Wneigh^T ----
    constexpr int CR = DOUT, NTW = (CR / 32 > 0) ? CR / 32 : 1, CG = CR / 4;
    __syncthreads();
    for (int e = tid; e < CR * K4; e += NT) {
        int r = e / K4, c4 = e % K4;
        ((uint4*)(Ws + r * SXA))[c4] = tf32x4(Wn4[r * K4 + c4]);
    }
    for (int e = tid; e < TM * (CR / 4); e += NT) {
        int row = e / (CR / 4), c4 = e % (CR / 4);
        int nd = node0 + row; if (nd >= nN) nd = nN - 1;
        ((float4*)(Gs + row * SXG))[c4] = ((const float4*)(gX + nd * W + 4 * DIN))[c4];
    }
    __syncthreads();
    float D[3][4][4];
#pragma unroll
    for (int mi = 0; mi < 3; mi++)
        for (int nt = 0; nt < NTW; nt++) {
            const float* pg = Gs + (MB + 16 * mi + gq) * SXG + CG * ng + 8 * nt + 2 * tq;
            D[mi][nt][0] = pg[0]; D[mi][nt][1] = pg[1];
            D[mi][nt][2] = pg[8 * SXG]; D[mi][nt][3] = pg[8 * SXG + 1];
        }
#pragma unroll 4
    for (int k0 = 0; k0 < DIN; k0 += 8) {
        u32 a[3][4], b[4][2];
#pragma unroll
        for (int mi = 0; mi < 3; mi++) {
            const float* pa = pA0 + 16 * mi * SXA + k0;
            a[mi][0] = __float_as_uint(pa[0]);
            a[mi][1] = __float_as_uint(pa[8 * SXA]);
            a[mi][2] = __float_as_uint(pa[4]);
            a[mi][3] = __float_as_uint(pa[8 * SXA + 4]);
        }
        for (int nt = 0; nt < NTW; nt++) {
            const float* pb = Ws + (CG * ng + 8 * nt + gq) * SXA + tq + k0;
            b[nt][0] = __float_as_uint(pb[0]);
            b[nt][1] = __float_as_uint(pb[4]);
#pragma unroll
            for (int mi = 0; mi < 3; mi++) mma8(D[mi][nt], a[mi], b[nt]);
        }
    }
    for (int nt = 0; nt < NTW; nt++) {
        int col = CG * ng + 8 * nt + 2 * tq;
#pragma unroll
        for (int mi = 0; mi < 3; mi++) {
            int r0 = node0 + MB + 16 * mi + gq;
            if (r0 < nN) {
                float v0 = D[mi][nt][0], v1 = D[mi][nt][1];
                if (RELU) { v0 = fmaxf(v0, 0.f); v1 = fmaxf(v1, 0.f); }
                fout[r0 * DOUT + col] = v0; fout[r0 * DOUT + col + 1] = v1;
            }
            if (r0 + 8 < nN) {
                float v2 = D[mi][nt][2], v3 = D[mi][nt][3];
                if (RELU) { v2 = fmaxf(v2, 0.f); v3 = fmaxf(v3, 0.f); }
                fout[(r0 + 8) * DOUT + col] = v2; fout[(r0 + 8) * DOUT + col + 1] = v3;
            }
        }
    }
}

extern "C" void kernel_launch(void* const* d_in, const int* in_sizes, int n_in,
                              void* d_out, int out_size) {
    const float* p  = (const float*)d_in[0];
    const int* nidx = (const int*)d_in[1];
    int nN = in_sizes[1] / KNB;

    float *fA, *fB, *gX;
    cudaGetSymbolAddress((void**)&fA, g_fA);
    cudaGetSymbolAddress((void**)&fB, g_fB);
    cudaGetSymbolAddress((void**)&gX, g_gX);

    auto smPre = [](int DIN, int DOUT) {
        return (144 * (DIN + 4) + 128 * (DIN + 4) + 4 * DIN + DOUT) * 4;
    };
    auto smRec = [](int DIN) {
        return (144 * (DIN + 4) + 128 * (DIN + 4) + 144 * 132) * 4;
    };
    cudaFuncSetAttribute(pre_k<64, 128>,  cudaFuncAttributeMaxDynamicSharedMemorySize, smPre(64, 128));
    cudaFuncSetAttribute(pre_k<128, 128>, cudaFuncAttributeMaxDynamicSharedMemorySize, smPre(128, 128));
    cudaFuncSetAttribute(pre_k<128, 32>,  cudaFuncAttributeMaxDynamicSharedMemorySize, smPre(128, 32));
    cudaFuncSetAttribute(rec_k<64, 128, true>,  cudaFuncAttributeMaxDynamicSharedMemorySize, smRec(64));
    cudaFuncSetAttribute(rec_k<128, 128, true>, cudaFuncAttributeMaxDynamicSharedMemorySize, smRec(128));
    cudaFuncSetAttribute(rec_k<128, 32, false>, cudaFuncAttributeMaxDynamicSharedMemorySize, smRec(128));

    build_feat0<<<(nN * 64 + 255) / 256, 256>>>(p, fA, nN);

    int grid = (nN + 143) / 144;
    // layer 0
    pre_k<64, 128><<<grid, 384, smPre(64, 128)>>>(
        fA, (const float*)d_in[2], (const float*)d_in[4], (const float*)d_in[5],
        (const float*)d_in[6], (const float*)d_in[8], gX, nN);
    rec_k<64, 128, true><<<grid, 384, smRec(64)>>>(
        gX, nidx, (const float*)d_in[3], (const float*)d_in[7], fB, nN);
    // layer 1
    pre_k<128, 128><<<grid, 384, smPre(128, 128)>>>(
        fB, (const float*)d_in[9], (const float*)d_in[11], (const float*)d_in[12],
        (const float*)d_in[13], (const float*)d_in[15], gX, nN);
    rec_k<128, 128, true><<<grid, 384, smRec(128)>>>(
        gX, nidx, (const float*)d_in[10], (const float*)d_in[14], fA, nN);
    // layer 2
    pre_k<128, 32><<<grid, 384, smPre(128, 32)>>>(
        fA, (const float*)d_in[16], (const float*)d_in[18], (const float*)d_in[19],
        (const float*)d_in[20], (const float*)d_in[22], gX, nN);
    rec_k<128, 32, false><<<grid, 384, smRec(128)>>>(
        gX, nidx, (const float*)d_in[17], (const float*)d_in[21], (float*)d_out, nN);
}

// round 11
// speedup vs baseline: 1.6185x; 1.1131x over previous
#include <cuda_runtime.h>
#define KNB 16
typedef unsigned u32;

__device__ __align__(256) float g_fA[20096 * 128];
__device__ __align__(256) float g_fB[20096 * 128];
__device__ __align__(256) float g_gX[20096 * 640];

__device__ __forceinline__ float tanha(float x) {
    float r; asm("tanh.approx.f32 %0, %1;" : "=f"(r) : "f"(x)); return r;
}
__device__ __forceinline__ float siga(float x) {
    return fmaf(tanha(0.5f * x), 0.5f, 0.5f);
}
__device__ __forceinline__ u32 tf32r(float f) {
    u32 r; asm("cvt.rna.tf32.f32 %0, %1;" : "=r"(r) : "f"(f)); return r;
}
__device__ __forceinline__ uint4 tf32x4(float4 v) {
    return make_uint4(tf32r(v.x), tf32r(v.y), tf32r(v.z), tf32r(v.w));
}
__device__ __forceinline__ void mma8(float* d, const u32* a, const u32* b) {
    asm volatile("mma.sync.aligned.m16n8k8.row.col.f32.tf32.tf32.f32 "
        "{%0,%1,%2,%3},{%4,%5,%6,%7},{%8,%9},{%0,%1,%2,%3};"
        : "+f"(d[0]), "+f"(d[1]), "+f"(d[2]), "+f"(d[3])
        : "r"(a[0]), "r"(a[1]), "r"(a[2]), "r"(a[3]), "r"(b[0]), "r"(b[1]));
}
// Gate-column permutation (see R10): thread (gq,tq) of warp ng owns all 4 gates
// of its units directly in its MMA output registers.
__device__ __forceinline__ int gmap(int c, int DIN) {
    int blk = c >> 5, w5 = c & 31;
    int nt = w5 >> 3, tq = (w5 >> 1) & 3, e = w5 & 1;
    return (2 * (nt & 1) + e) * DIN + blk * 8 + (nt >> 1) * 4 + tq;
}

__global__ void build_feat0(const float* __restrict__ p, float* __restrict__ f0, int nN) {
    int i = blockIdx.x * blockDim.x + threadIdx.x;
    if (i >= nN * 64) return;
    int node = i >> 6, k = i & 63;
    f0[i] = (k == 0) ? (16.0f / (float)nN) : p[node * 63 + (k - 1)];
}

// ---------------- precompute: gX[n] = feat[n] @ [Wih(permuted) | Wself]^T + bias ----------------
template <int DIN, int DOUT>
__global__ __launch_bounds__(384, 1)
void pre_k(const float* __restrict__ feat,
           const float* __restrict__ Wih, const float* __restrict__ bih,
           const float* __restrict__ bhh, const float* __restrict__ Wself,
           const float* __restrict__ bo, float* __restrict__ gX, int nN)
{
    constexpr int TM = 144, NT = 384, K4 = DIN / 4, SXA = DIN + 4, W = 4 * DIN + DOUT;
    extern __shared__ float sm[];
    float* Xs = sm;
    float* Ws = sm + TM * SXA;
    float* CB = Ws + 128 * SXA;

    const int tid = threadIdx.x, lane = tid & 31, w = tid >> 5;
    const int gq = lane >> 2, tq = lane & 3, mg = w % 3, ng = w / 3, MB = 48 * mg;
    const int node0 = blockIdx.x * TM;
    const float4* fin4 = (const float4*)feat;
    const float4* Wi4 = (const float4*)Wih;
    const float4* Wsf4 = (const float4*)Wself;

    for (int e = tid; e < 4 * DIN; e += NT) {
        int sr = gmap(e, DIN);
        CB[e] = bih[sr] + bhh[sr];
    }
    for (int e = tid; e < DOUT; e += NT) CB[4 * DIN + e] = bo[e];
    for (int e = tid; e < TM * K4; e += NT) {
        int row = e / K4, c4 = e % K4;
        int nd = node0 + row; if (nd >= nN) nd = nN - 1;
        ((uint4*)(Xs + row * SXA))[c4] = tf32x4(fin4[nd * K4 + c4]);
    }
    const float* pA0 = Xs + (MB + gq) * SXA + tq;

    for (int c0 = 0; c0 < W; c0 += 128) {
        const int CR = (W - c0 < 128) ? (W - c0) : 128;
        const int NTW = CR / 32, CG = CR / 4;
        __syncthreads();
        for (int e = tid; e < CR * K4; e += NT) {
            int r = e / K4, c4 = e % K4;
            int gc = c0 + r;
            float4 v = (gc < 4 * DIN) ? Wi4[gmap(gc, DIN) * K4 + c4]
                                      : Wsf4[(gc - 4 * DIN) * K4 + c4];
            ((uint4*)(Ws + r * SXA))[c4] = tf32x4(v);
        }
        __syncthreads();
        float D[3][4][4];
        for (int nt = 0; nt < NTW; nt++) {
            float b0 = CB[c0 + CG * ng + 8 * nt + 2 * tq];
            float b1 = CB[c0 + CG * ng + 8 * nt + 2 * tq + 1];
#pragma unroll
            for (int mi = 0; mi < 3; mi++) {
                D[mi][nt][0] = b0; D[mi][nt][1] = b1;
                D[mi][nt][2] = b0; D[mi][nt][3] = b1;
            }
        }
#pragma unroll 4
        for (int k0 = 0; k0 < DIN; k0 += 8) {
            u32 a[3][4], b[4][2];
#pragma unroll
            for (int mi = 0; mi < 3; mi++) {
                const float* pa = pA0 + 16 * mi * SXA + k0;
                a[mi][0] = __float_as_uint(pa[0]);
                a[mi][1] = __float_as_uint(pa[8 * SXA]);
                a[mi][2] = __float_as_uint(pa[4]);
                a[mi][3] = __float_as_uint(pa[8 * SXA + 4]);
            }
            for (int nt = 0; nt < NTW; nt++) {
                const float* pb = Ws + (CG * ng + 8 * nt + gq) * SXA + tq + k0;
                b[nt][0] = __float_as_uint(pb[0]);
                b[nt][1] = __float_as_uint(pb[4]);
#pragma unroll
                for (int mi = 0; mi < 3; mi++) mma8(D[mi][nt], a[mi], b[nt]);
            }
        }
        for (int nt = 0; nt < NTW; nt++) {
            int col = c0 + CG * ng + 8 * nt + 2 * tq;
#pragma unroll
            for (int mi = 0; mi < 3; mi++) {
                int r0 = node0 + MB + 16 * mi + gq;
                if (r0 < nN) {
                    gX[r0 * W + col] = D[mi][nt][0];
                    gX[r0 * W + col + 1] = D[mi][nt][1];
                }
                if (r0 + 8 < nN) {
                    gX[(r0 + 8) * W + col] = D[mi][nt][2];
                    gX[(r0 + 8) * W + col + 1] = D[mi][nt][3];
                }
            }
        }
    }
}

// ---------------- recurrent: h(t) = LSTM(h(t-1) @ Whh^T + direct-LDG x-gates) ----------------
// Xs double-buffered; x-gates loaded straight from gX into registers (latency
// hidden under the k-loop) and added in the epilogue.
template <int DIN, int DOUT, bool RELU>
__global__ __launch_bounds__(384, 1)
void rec_k(const float* __restrict__ gX, const int* __restrict__ nidx,
           const float* __restrict__ Whh, const float* __restrict__ Wneigh,
           float* __restrict__ fout, int nN)
{
    constexpr int TM = 144, NT = 384, K4 = DIN / 4, SXA = DIN + 4;
    constexpr int W = 4 * DIN + DOUT, NCHG = (4 * DIN) / 128;
    extern __shared__ float sm[];
    float* Xs0 = sm;                    // TM x SXA : h buffer A
    float* Xs1 = sm + TM * SXA;         // TM x SXA : h buffer B
    float* Ws  = sm + 2 * TM * SXA;     // 128 x SXA : Whh chunk / Wneigh

    const int tid = threadIdx.x, lane = tid & 31, w = tid >> 5;
    const int gq = lane >> 2, tq = lane & 3, mg = w % 3, ng = w / 3, MB = 48 * mg;
    const int node0 = blockIdx.x * TM;
    const float4* Wh4 = (const float4*)Whh;
    const float4* Wn4 = (const float4*)Wneigh;

    for (int e = tid; e < TM * K4; e += NT)
        ((uint4*)(Xs0 + (e / K4) * SXA))[e % K4] = make_uint4(0, 0, 0, 0);

    float c_loc[NCHG][12];
#pragma unroll 1
    for (int ci = 0; ci < NCHG; ci++)
#pragma unroll
        for (int i = 0; i < 12; i++) c_loc[ci][i] = 0.f;

    for (int t = 0; t < KNB; t++) {
        int srcs[6];
#pragma unroll
        for (int mi = 0; mi < 3; mi++)
#pragma unroll
            for (int r2 = 0; r2 < 2; r2++) {
                int nd = node0 + MB + 16 * mi + gq + 8 * r2;
                if (nd >= nN) nd = nN - 1;
                srcs[mi * 2 + r2] = nidx[nd * KNB + t];
            }
        const float* Xc = (t & 1) ? Xs1 : Xs0;
        float* Xn = (t & 1) ? Xs0 : Xs1;
        const float* pA0 = Xc + (MB + gq) * SXA + tq;

#pragma unroll 1
        for (int ci = 0; ci < NCHG; ci++) {
            __syncthreads();   // prior Ws reads done; (ci==0) h(t-1) visible
            for (int e = tid; e < 128 * K4; e += NT) {
                int r = e / K4, c4 = e % K4;
                ((uint4*)(Ws + r * SXA))[c4] =
                    tf32x4(Wh4[gmap(ci * 128 + r, DIN) * K4 + c4]);
            }
            __syncthreads();
            // x-gates for this chunk: direct LDG, consumed after the k-loop
            float2 gxv[3][4][2];
#pragma unroll
            for (int mi = 0; mi < 3; mi++)
#pragma unroll
                for (int r2 = 0; r2 < 2; r2++) {
                    const float2* g2 = (const float2*)(gX +
                        (size_t)srcs[mi * 2 + r2] * W + ci * 128 + 32 * ng + 2 * tq);
#pragma unroll
                    for (int nt = 0; nt < 4; nt++) gxv[mi][nt][r2] = g2[4 * nt];
                }
            float D[3][4][4];
#pragma unroll
            for (int mi = 0; mi < 3; mi++)
#pragma unroll
                for (int nt = 0; nt < 4; nt++)
#pragma unroll
                    for (int j = 0; j < 4; j++) D[mi][nt][j] = 0.f;
#pragma unroll 4
            for (int k0 = 0; k0 < DIN; k0 += 8) {
                u32 a[3][4], b[4][2];
#pragma unroll
                for (int mi = 0; mi < 3; mi++) {
                    const float* pa = pA0 + 16 * mi * SXA + k0;
                    a[mi][0] = __float_as_uint(pa[0]);
                    a[mi][1] = __float_as_uint(pa[8 * SXA]);
                    a[mi][2] = __float_as_uint(pa[4]);
                    a[mi][3] = __float_as_uint(pa[8 * SXA + 4]);
                }
#pragma unroll
                for (int nt = 0; nt < 4; nt++) {
                    const float* pb = Ws + (32 * ng + 8 * nt + gq) * SXA + tq + k0;
                    b[nt][0] = __float_as_uint(pb[0]);
                    b[nt][1] = __float_as_uint(pb[4]);
#pragma unroll
                    for (int mi = 0; mi < 3; mi++) mma8(D[mi][nt], a[mi], b[nt]);
                }
            }
            // epilogue: add x-gates, LSTM cell update, write h into Xn
#pragma unroll
            for (int mi = 0; mi < 3; mi++)
#pragma unroll
                for (int up = 0; up < 2; up++)
#pragma unroll
                    for (int r2 = 0; r2 < 2; r2++) {
                        float gi = D[mi][2 * up][2 * r2]     + gxv[mi][2 * up][r2].x;
                        float gf = D[mi][2 * up][2 * r2 + 1] + gxv[mi][2 * up][r2].y;
                        float gg = D[mi][2 * up + 1][2 * r2]     + gxv[mi][2 * up + 1][r2].x;
                        float go = D[mi][2 * up + 1][2 * r2 + 1] + gxv[mi][2 * up + 1][r2].y;
                        int s = (mi * 2 + up) * 2 + r2;
                        float cc = siga(gf) * c_loc[ci][s] + siga(gi) * tanha(gg);
                        c_loc[ci][s] = cc;
                        float hv = siga(go) * tanha(cc);
                        Xn[(MB + 16 * mi + gq + 8 * r2) * SXA +
                           ci * 32 + 8 * ng + 4 * up + tq] = __uint_as_float(tf32r(hv));
                    }
        }
    }

    // ---- FC: out = selfX (precomputed, bias folded) + h_final @ Wneigh^T ----
    constexpr int NTW = DOUT / 32, CG = DOUT / 4;
    const float* Xf = (KNB & 1) ? Xs1 : Xs0;
    const float* pAf = Xf + (MB + gq) * SXA + tq;
    __syncthreads();
    for (int e = tid; e < DOUT * K4; e += NT) {
        int r = e / K4, c4 = e % K4;
        ((uint4*)(Ws + r * SXA))[c4] = tf32x4(Wn4[r * K4 + c4]);
    }
    __syncthreads();
    float2 sxv[3][4][2];
#pragma unroll
    for (int mi = 0; mi < 3; mi++)
#pragma unroll
        for (int r2 = 0; r2 < 2; r2++) {
            int nd = node0 + MB + 16 * mi + gq + 8 * r2;
            if (nd >= nN) nd = nN - 1;
            const float2* g2 = (const float2*)(gX +
                (size_t)nd * W + 4 * DIN + CG * ng + 2 * tq);
            for (int nt = 0; nt < NTW; nt++) sxv[mi][nt][r2] = g2[4 * nt];
        }
    float D[3][4][4];
#pragma unroll
    for (int mi = 0; mi < 3; mi++)
        for (int nt = 0; nt < NTW; nt++)
#pragma unroll
            for (int j = 0; j < 4; j++) D[mi][nt][j] = 0.f;
#pragma unroll 4
    for (int k0 = 0; k0 < DIN; k0 += 8) {
        u32 a[3][4], b[4][2];
#pragma unroll
        for (int mi = 0; mi < 3; mi++) {
            const float* pa = pAf + 16 * mi * SXA + k0;
            a[mi][0] = __float_as_uint(pa[0]);
            a[mi][1] = __float_as_uint(pa[8 * SXA]);
            a[mi][2] = __float_as_uint(pa[4]);
            a[mi][3] = __float_as_uint(pa[8 * SXA + 4]);
        }
        for (int nt = 0; nt < NTW; nt++) {
            const float* pb = Ws + (CG * ng + 8 * nt + gq) * SXA + tq + k0;
            b[nt][0] = __float_as_uint(pb[0]);
            b[nt][1] = __float_as_uint(pb[4]);
#pragma unroll
            for (int mi = 0; mi < 3; mi++) mma8(D[mi][nt], a[mi], b[nt]);
        }
    }
    for (int nt = 0; nt < NTW; nt++) {
        int col = CG * ng + 8 * nt + 2 * tq;
#pragma unroll
        for (int mi = 0; mi < 3; mi++) {
            int r0 = node0 + MB + 16 * mi + gq;
            if (r0 < nN) {
                float v0 = D[mi][nt][0] + sxv[mi][nt][0].x;
                float v1 = D[mi][nt][1] + sxv[mi][nt][0].y;
                if (RELU) { v0 = fmaxf(v0, 0.f); v1 = fmaxf(v1, 0.f); }
                fout[r0 * DOUT + col] = v0; fout[r0 * DOUT + col + 1] = v1;
            }
            if (r0 + 8 < nN) {
                float v2 = D[mi][nt][2] + sxv[mi][nt][1].x;
                float v3 = D[mi][nt][3] + sxv[mi][nt][1].y;
                if (RELU) { v2 = fmaxf(v2, 0.f); v3 = fmaxf(v3, 0.f); }
                fout[(r0 + 8) * DOUT + col] = v2; fout[(r0 + 8) * DOUT + col + 1] = v3;
            }
        }
    }
}

extern "C" void kernel_launch(void* const* d_in, const int* in_sizes, int n_in,
                              void* d_out, int out_size) {
    const float* p  = (const float*)d_in[0];
    const int* nidx = (const int*)d_in[1];
    int nN = in_sizes[1] / KNB;

    float *fA, *fB, *gX;
    cudaGetSymbolAddress((void**)&fA, g_fA);
    cudaGetSymbolAddress((void**)&fB, g_fB);
    cudaGetSymbolAddress((void**)&gX, g_gX);

    auto smPre = [](int DIN, int DOUT) {
        return (144 * (DIN + 4) + 128 * (DIN + 4) + 4 * DIN + DOUT) * 4;
    };
    auto smRec = [](int DIN) {
        return (2 * 144 * (DIN + 4) + 128 * (DIN + 4)) * 4;
    };
    cudaFuncSetAttribute(pre_k<64, 128>,  cudaFuncAttributeMaxDynamicSharedMemorySize, smPre(64, 128));
    cudaFuncSetAttribute(pre_k<128, 128>, cudaFuncAttributeMaxDynamicSharedMemorySize, smPre(128, 128));
    cudaFuncSetAttribute(pre_k<128, 32>,  cudaFuncAttributeMaxDynamicSharedMemorySize, smPre(128, 32));
    cudaFuncSetAttribute(rec_k<64, 128, true>,  cudaFuncAttributeMaxDynamicSharedMemorySize, smRec(64));
    cudaFuncSetAttribute(rec_k<128, 128, true>, cudaFuncAttributeMaxDynamicSharedMemorySize, smRec(128));
    cudaFuncSetAttribute(rec_k<128, 32, false>, cudaFuncAttributeMaxDynamicSharedMemorySize, smRec(128));

    build_feat0<<<(nN * 64 + 255) / 256, 256>>>(p, fA, nN);

    int grid = (nN + 143) / 144;
    // layer 0
    pre_k<64, 128><<<grid, 384, smPre(64, 128)>>>(
        fA, (const float*)d_in[2], (const float*)d_in[4], (const float*)d_in[5],
        (const float*)d_in[6], (const float*)d_in[8], gX, nN);
    rec_k<64, 128, true><<<grid, 384, smRec(64)>>>(
        gX, nidx, (const float*)d_in[3], (const float*)d_in[7], fB, nN);
    // layer 1
    pre_k<128, 128><<<grid, 384, smPre(128, 128)>>>(
        fB, (const float*)d_in[9], (const float*)d_in[11], (const float*)d_in[12],
        (const float*)d_in[13], (const float*)d_in[15], gX, nN);
    rec_k<128, 128, true><<<grid, 384, smRec(128)>>>(
        gX, nidx, (const float*)d_in[10], (const float*)d_in[14], fA, nN);
    // layer 2
    pre_k<128, 32><<<grid, 384, smPre(128, 32)>>>(
        fA, (const float*)d_in[16], (const float*)d_in[18], (const float*)d_in[19],
        (const float*)d_in[20], (const float*)d_in[22], gX, nN);
    rec_k<128, 32, false><<<grid, 384, smRec(128)>>>(
        gX, nidx, (const float*)d_in[17], (const float*)d_in[21], (float*)d_out, nN);
}